// round 1
// baseline (speedup 1.0000x reference)
#include <cuda_runtime.h>

#define B_    8
#define P_    75
#define HW_   196
#define C_    384
#define H_    6
#define D_    64
#define M_    25
#define SCALE_ 0.125f
#define KSTR  70   // kv smem row stride in floats (keeps LDS.64 conflicts <= 2-way in both phases)

// smem layout (floats): kv[196*70] | qs[25*64] | adup[25*196 float2] | rowscale[32]
#define SMEM_FLOATS (HW_*KSTR + M_*D_ + M_*HW_*2 + 32)
#define SMEM_BYTES  (SMEM_FLOATS * 4)

typedef unsigned long long u64;

__device__ __forceinline__ u64 fma2(u64 a, u64 b, u64 c) {
    u64 d;
    asm("fma.rn.f32x2 %0, %1, %2, %3;" : "=l"(d) : "l"(a), "l"(b), "l"(c));
    return d;
}
__device__ __forceinline__ void unpack2(u64 v, float& lo, float& hi) {
    asm("mov.b64 {%0, %1}, %2;" : "=f"(lo), "=f"(hi) : "l"(v));
}

__global__ void __launch_bounds__(256, 2)
tokenqkv_attn_kernel(const float* __restrict__ xq_g,
                     const float* __restrict__ xs_g,
                     float* __restrict__ out) {
    extern __shared__ float sm[];
    float*  kvs      = sm;                          // 196 x KSTR
    float*  qss      = sm + HW_ * KSTR;             // 25 x 64
    float2* adup     = (float2*)(qss + M_ * D_);    // 25 x 196 duplicated attn
    float*  rowscale = (float*)(adup + M_ * HW_);   // 25 (padded)

    const int tid = threadIdx.x;
    const int h = blockIdx.x, p = blockIdx.y, b = blockIdx.z;

    const float* xq = xq_g + ((size_t)(b * P_ + p)) * HW_ * C_ + h * D_;
    const float* xs = xs_g + (size_t)b * M_ * C_ + h * D_;

    // ---- stage kv tile (196 x 64) and qs (25 x 64) ----
    for (int i = tid; i < HW_ * (D_ / 2); i += 256) {
        int w = i >> 5, c = (i & 31) << 1;
        *(float2*)&kvs[w * KSTR + c] = *(const float2*)(xq + (size_t)w * C_ + c);
    }
    for (int i = tid; i < M_ * (D_ / 4); i += 256) {
        int m = i >> 4, c = (i & 15) << 2;
        *(float4*)&qss[m * D_ + c] = *(const float4*)(xs + (size_t)m * C_ + c);
    }
    __syncthreads();

    // ---- QK: logits[m][w] = sum_d qs[m][d]*kv[w][d] ----
    // 196 threads: each owns 2 w-columns, 13 (or 12) m-rows, f32x2 accumulation over d.
    if (tid < HW_) {
        const int wp = tid % 98;
        const int mg = tid / 98;        // 0 or 1
        const int w0 = wp * 2, w1 = w0 + 1;
        const int mbase = mg * 13;      // mg0: m 0..12, mg1: m 13..24

        u64 acc0[13], acc1[13];
        #pragma unroll
        for (int j = 0; j < 13; ++j) { acc0[j] = 0ULL; acc1[j] = 0ULL; }

        const u64* kv0 = (const u64*)&kvs[w0 * KSTR];
        const u64* kv1 = (const u64*)&kvs[w1 * KSTR];
        const u64* qb  = (const u64*)qss;

        #pragma unroll 4
        for (int d2 = 0; d2 < D_ / 2; ++d2) {
            const u64 ka = kv0[d2];
            const u64 kb = kv1[d2];
            #pragma unroll
            for (int j = 0; j < 13; ++j) {
                if (mbase + j < M_) {
                    u64 q = qb[(mbase + j) * (D_ / 2) + d2];
                    acc0[j] = fma2(q, ka, acc0[j]);
                    acc1[j] = fma2(q, kb, acc1[j]);
                }
            }
        }
        #pragma unroll
        for (int j = 0; j < 13; ++j) {
            if (mbase + j < M_) {
                int m = mbase + j;
                float lo, hi;
                unpack2(acc0[j], lo, hi);
                ((float*)(adup + m * HW_ + w0))[0] = lo + hi;
                unpack2(acc1[j], lo, hi);
                ((float*)(adup + m * HW_ + w1))[0] = lo + hi;
            }
        }
    }
    __syncthreads();

    // ---- softmax over w per row m (SCALE folded into exp); store exp duplicated {e,e} ----
    {
        const int lane = tid & 31, warp = tid >> 5;
        for (int m = warp; m < M_; m += 8) {
            float2* row = adup + m * HW_;
            float vmax = -1e30f;
            for (int k = lane; k < HW_; k += 32) vmax = fmaxf(vmax, row[k].x);
            #pragma unroll
            for (int off = 16; off; off >>= 1)
                vmax = fmaxf(vmax, __shfl_xor_sync(0xffffffffu, vmax, off));
            float s = 0.0f;
            for (int k = lane; k < HW_; k += 32) {
                float e = __expf((row[k].x - vmax) * SCALE_);
                row[k] = make_float2(e, e);
                s += e;
            }
            #pragma unroll
            for (int off = 16; off; off >>= 1)
                s += __shfl_xor_sync(0xffffffffu, s, off);
            if (lane == 0) rowscale[m] = 1.0f / s;
        }
    }
    __syncthreads();

    // ---- AV: o[m][d] = rowscale[m] * sum_w exp[m][w]*kv[w][d] ----
    // 256 threads: dq = d-quad (4 floats = 2 f32x2 pairs), mg -> rows {mg, mg+16}
    {
        const int dq = tid & 15;
        const int mg = tid >> 4;
        const int m0 = mg, m1 = mg + 16;
        const bool two = (m1 < M_);

        u64 a001 = 0ULL, a023 = 0ULL, a101 = 0ULL, a123 = 0ULL;
        const u64* kvb = (const u64*)kvs;   // index: w*(KSTR/2) + dq*2
        const u64* A   = (const u64*)adup;  // index: m*HW_ + w  (value {e,e})

        #pragma unroll 4
        for (int w = 0; w < HW_; ++w) {
            const u64 k01 = kvb[w * (KSTR / 2) + dq * 2];
            const u64 k23 = kvb[w * (KSTR / 2) + dq * 2 + 1];
            const u64 am0 = A[m0 * HW_ + w];
            a001 = fma2(am0, k01, a001);
            a023 = fma2(am0, k23, a023);
            if (two) {
                const u64 am1 = A[m1 * HW_ + w];
                a101 = fma2(am1, k01, a101);
                a123 = fma2(am1, k23, a123);
            }
        }

        const size_t obase = ((size_t)(b * P_ + p) * M_) * C_ + h * D_ + dq * 4;
        {
            float s0 = rowscale[m0];
            float x, y, z, w4;
            unpack2(a001, x, y);
            unpack2(a023, z, w4);
            float4 r = make_float4(x * s0, y * s0, z * s0, w4 * s0);
            *(float4*)(out + obase + (size_t)m0 * C_) = r;
        }
        if (two) {
            float s1 = rowscale[m1];
            float x, y, z, w4;
            unpack2(a101, x, y);
            unpack2(a123, z, w4);
            float4 r = make_float4(x * s1, y * s1, z * s1, w4 * s1);
            *(float4*)(out + obase + (size_t)m1 * C_) = r;
        }
    }
}

// o_support = x_support (exact copy), appended after o_query
__global__ void tokenqkv_support_copy(const float* __restrict__ xs, float* __restrict__ out) {
    int i = blockIdx.x * 256 + threadIdx.x;  // 76800/4 = 19200 float4
    if (i < (B_ * M_ * C_) / 4)
        ((float4*)out)[i] = ((const float4*)xs)[i];
}

extern "C" void kernel_launch(void* const* d_in, const int* in_sizes, int n_in,
                              void* d_out, int out_size) {
    const float* xq = (const float*)d_in[0];   // (8,5,15,196,384)
    const float* xs = (const float*)d_in[1];   // (8,25,384)
    float* out = (float*)d_out;

    cudaFuncSetAttribute(tokenqkv_attn_kernel,
                         cudaFuncAttributeMaxDynamicSharedMemorySize, SMEM_BYTES);

    dim3 grid(H_, P_, B_);
    tokenqkv_attn_kernel<<<grid, 256, SMEM_BYTES>>>(xq, xs, out);

    const size_t oq_elems = (size_t)B_ * P_ * M_ * C_;  // 5,760,000
    tokenqkv_support_copy<<<(B_ * M_ * C_ / 4 + 255) / 256, 256>>>(xs, out + oq_elems);
}

// round 2
// speedup vs baseline: 1.4096x; 1.4096x over previous
#include <cuda_runtime.h>

typedef unsigned long long u64;

#define B_    8
#define P_    75
#define HW_   196
#define C_    384
#define H_    6
#define D_    64
#define M_    25
#define SCALE_ 0.125f

#define KSTR  68    // kv row stride (floats): 68%32=4 -> LDS.128 conflict-free
#define CSTR  200   // logits row stride
#define ASTR  28    // aT row stride (m padded 25->28, 112B, 16B-aligned)

#define OFF_QS (HW_*KSTR)
#define OFF_C  (OFF_QS + M_*D_)
#define OFF_AT (OFF_C + M_*CSTR)
#define OFF_RS (OFF_AT + HW_*ASTR)
#define SMEM_FLOATS (OFF_RS + 32)
#define SMEM_BYTES  (SMEM_FLOATS * 4)

__device__ __forceinline__ u64 fma2(u64 a, u64 b, u64 c) {
    u64 d; asm("fma.rn.f32x2 %0, %1, %2, %3;" : "=l"(d) : "l"(a), "l"(b), "l"(c)); return d;
}
__device__ __forceinline__ u64 add2(u64 a, u64 b) {
    u64 d; asm("add.rn.f32x2 %0, %1, %2;" : "=l"(d) : "l"(a), "l"(b)); return d;
}
__device__ __forceinline__ u64 splat(float x) {
    u64 d; asm("mov.b64 %0, {%1, %1};" : "=l"(d) : "f"(x)); return d;
}
__device__ __forceinline__ float hsum(u64 v) {
    float lo, hi; asm("mov.b64 {%0, %1}, %2;" : "=f"(lo), "=f"(hi) : "l"(v)); return lo + hi;
}
__device__ __forceinline__ float2 unp(u64 v) {
    float lo, hi; asm("mov.b64 {%0, %1}, %2;" : "=f"(lo), "=f"(hi) : "l"(v)); return make_float2(lo, hi);
}

// QK: c[m][w] = sum_d q[m][d]*kv[w][d], packed over d, horizontal add at end.
// Warp covers MT m-rows x 98 w (its group) via 4 w-slots (lane + 32j; slot 3 = 2 leftover cols).
template<int MT>
__device__ __forceinline__ void qk_loop(const float* __restrict__ kvs,
                                        const float* __restrict__ qss,
                                        float* __restrict__ cbuf,
                                        int mbase, int wbase, int lane)
{
    u64 acc[MT][4];
    #pragma unroll
    for (int mi = 0; mi < MT; mi++) { acc[mi][0] = 0; acc[mi][1] = 0; acc[mi][2] = 0; acc[mi][3] = 0; }

    const int wj0 = wbase + lane;
    const int wj1 = wbase + 32 + lane;
    const int wj2 = wbase + 64 + lane;
    const int wj3 = wbase + 96 + (lane & 1);   // all lanes load valid addr; only lanes 0,1 write

    #pragma unroll 1
    for (int d4 = 0; d4 < 16; d4++) {
        ulonglong2 q[MT];
        #pragma unroll
        for (int mi = 0; mi < MT; mi++)
            q[mi] = *(const ulonglong2*)&qss[(mbase + mi) * D_ + d4 * 4];
        const int wj[4] = {wj0, wj1, wj2, wj3};
        #pragma unroll
        for (int j = 0; j < 4; j++) {
            ulonglong2 k = *(const ulonglong2*)&kvs[wj[j] * KSTR + d4 * 4];
            #pragma unroll
            for (int mi = 0; mi < MT; mi++) {
                acc[mi][j] = fma2(q[mi].x, k.x, acc[mi][j]);
                acc[mi][j] = fma2(q[mi].y, k.y, acc[mi][j]);
            }
        }
    }
    #pragma unroll
    for (int mi = 0; mi < MT; mi++) {
        cbuf[(mbase + mi) * CSTR + wj0] = hsum(acc[mi][0]);
        cbuf[(mbase + mi) * CSTR + wj1] = hsum(acc[mi][1]);
        cbuf[(mbase + mi) * CSTR + wj2] = hsum(acc[mi][2]);
    }
    if (lane < 2) {
        #pragma unroll
        for (int mi = 0; mi < MT; mi++)
            cbuf[(mbase + mi) * CSTR + wj3] = hsum(acc[mi][3]);
    }
}

__global__ void __launch_bounds__(256, 2)
tokenqkv_attn_kernel(const float* __restrict__ xq_g,
                     const float* __restrict__ xs_g,
                     float* __restrict__ out)
{
    extern __shared__ float sm[];
    float* kvs  = sm;                // 196 x 68
    float* qss  = sm + OFF_QS;       // 25 x 64
    float* cbuf = sm + OFF_C;        // 25 x 200 logits
    float* aT   = sm + OFF_AT;       // 196 x 28 (exp, transposed)
    float* rs   = sm + OFF_RS;       // 25 row 1/sum

    const int tid = threadIdx.x, lane = tid & 31, wid = tid >> 5;
    const int h = blockIdx.x, p = blockIdx.y, b = blockIdx.z;

    const float* xq  = xq_g + ((size_t)(b * P_ + p)) * HW_ * C_ + h * D_;
    const float* xsh = xs_g + (size_t)b * M_ * C_ + h * D_;

    // ---- stage kv (196x64) and qs (25x64) ----
    for (int i = tid; i < HW_ * 16; i += 256) {
        int w = i >> 4, c = (i & 15) << 2;
        *(float4*)&kvs[w * KSTR + c] = *(const float4*)(xq + (size_t)w * C_ + c);
    }
    for (int i = tid; i < M_ * 16; i += 256) {
        int m = i >> 4, c = (i & 15) << 2;
        *(float4*)&qss[m * D_ + c] = *(const float4*)(xsh + (size_t)m * C_ + c);
    }
    // ---- fold o_support copy into the 8 (h==0,p==0) blocks ----
    if (h == 0 && p == 0) {
        const float4* src = (const float4*)(xs_g + (size_t)b * M_ * C_);
        float4* dst = (float4*)(out + (size_t)B_ * P_ * M_ * C_ + (size_t)b * M_ * C_);
        for (int i = tid; i < M_ * C_ / 4; i += 256) dst[i] = src[i];
    }
    __syncthreads();

    // ---- QK: 2 w-groups x 4 m-warps (7,6,6,6) ----
    {
        const int grp = wid >> 2, mw = wid & 3;
        const int wbase = grp * 98;
        if      (mw == 0) qk_loop<7>(kvs, qss, cbuf, 0,  wbase, lane);
        else if (mw == 1) qk_loop<6>(kvs, qss, cbuf, 7,  wbase, lane);
        else if (mw == 2) qk_loop<6>(kvs, qss, cbuf, 13, wbase, lane);
        else              qk_loop<6>(kvs, qss, cbuf, 19, wbase, lane);
    }
    __syncthreads();

    // ---- softmax per m-row; write exp transposed into aT[w][m] ----
    for (int r = wid; r < M_; r += 8) {
        const float* crow = cbuf + r * CSTR;
        float vmax = -1e30f;
        for (int k = lane; k < HW_; k += 32) vmax = fmaxf(vmax, crow[k]);
        #pragma unroll
        for (int o = 16; o; o >>= 1) vmax = fmaxf(vmax, __shfl_xor_sync(0xffffffffu, vmax, o));
        float s = 0.0f;
        for (int k = lane; k < HW_; k += 32) {
            float e = __expf((crow[k] - vmax) * SCALE_);
            aT[k * ASTR + r] = e;
            s += e;
        }
        #pragma unroll
        for (int o = 16; o; o >>= 1) s += __shfl_xor_sync(0xffffffffu, s, o);
        if (lane == 0) rs[r] = 1.0f / s;
    }
    __syncthreads();

    // ---- AV: warps split w; each warp holds all 25 m-accs; lane = d-pair ----
    u64 acc[M_];
    #pragma unroll
    for (int m = 0; m < M_; m++) acc[m] = 0;
    {
        const int ws = (HW_ * wid) >> 3, we = (HW_ * (wid + 1)) >> 3;
        for (int w = ws; w < we; w++) {
            float a[28];
            #pragma unroll
            for (int g = 0; g < 7; g++)
                *(float4*)&a[g * 4] = *(const float4*)&aT[w * ASTR + g * 4];
            u64 k = *(const u64*)&kvs[w * KSTR + 2 * lane];
            #pragma unroll
            for (int m = 0; m < M_; m++)
                acc[m] = fma2(splat(a[m]), k, acc[m]);
        }
    }
    __syncthreads();   // everyone done reading kv/aT -> safe to alias kv with partials

    // ---- cross-warp reduction via smem partials (aliased into kv region) ----
    u64* part = (u64*)sm;   // 8 x 800 u64 = 51.2KB <= kv region 53.3KB
    #pragma unroll
    for (int m = 0; m < M_; m++)
        part[wid * 800 + m * 32 + lane] = acc[m];
    __syncthreads();

    float* outb = out + ((size_t)(b * P_ + p) * M_) * C_ + h * D_;
    for (int base = tid; base < 800; base += 256) {
        u64 s = part[base];
        #pragma unroll
        for (int k2 = 1; k2 < 8; k2++) s = add2(s, part[k2 * 800 + base]);
        int m = base >> 5, dp = base & 31;
        float sc = rs[m];
        float2 v = unp(s);
        v.x *= sc; v.y *= sc;
        *(float2*)&outb[(size_t)m * C_ + 2 * dp] = v;
    }
}

extern "C" void kernel_launch(void* const* d_in, const int* in_sizes, int n_in,
                              void* d_out, int out_size) {
    const float* xq = (const float*)d_in[0];   // (8,5,15,196,384)
    const float* xs = (const float*)d_in[1];   // (8,25,384)
    float* out = (float*)d_out;

    cudaFuncSetAttribute(tokenqkv_attn_kernel,
                         cudaFuncAttributeMaxDynamicSharedMemorySize, SMEM_BYTES);

    dim3 grid(H_, P_, B_);
    tokenqkv_attn_kernel<<<grid, 256, SMEM_BYTES>>>(xq, xs, out);
}